// round 1
// baseline (speedup 1.0000x reference)
#include <cuda_runtime.h>
#include <cuda_bf16.h>

#define FULLMASK 0xffffffffu

// CTC batch cost, forward algorithm in linear domain with exact power-of-2
// rescaling. One warp per batch element; 3 extended-label states per lane
// (lanes 0..21 hold states 0..65, state 65 is a dummy that stays 0).
__global__ __launch_bounds__(64, 1)
void ctc_fwd_kernel(const int* __restrict__ y_true,
                    const float* __restrict__ y_pred,
                    float* __restrict__ out)
{
    constexpr int   T      = 256;
    constexpr int   C      = 1024;
    constexpr int   L      = 32;
    constexpr int   S      = 65;     // 2*L + 1
    constexpr int   BLANK  = C - 1;
    constexpr float PRE    = 512.0f; // 2^9 per-step prescale (keeps alphas ~O(1))
    constexpr int   PRE_E  = 9;
    constexpr float EPS    = 1e-7f;
    constexpr float EPS_S  = EPS * PRE;

    const int lane = threadIdx.x & 31;
    const int b    = blockIdx.x * 2 + (threadIdx.x >> 5);   // grid 128 x 2 warps = 256

    // lane j holds label[j]
    const int lab = y_true[b * L + lane];
    const unsigned nzm = __ballot_sync(FULLMASK, lab != 0);
    const int len = __popc(nzm);

    const int s0 = 3 * lane, s1 = s0 + 1, s2 = s0 + 2;

    // Per-state class index and skip-transition allow flag.
    // ext[s] = blank for even s, label[(s-1)/2] for odd s.
    // allow_skip[s] = (s odd) && (s<3 || label[j] != label[j-1]).
    int   cls0, cls1, cls2;
    float al0, al1, al2;
#define STATE_SETUP(s, cls, al) {                                   \
        int j  = ((s) - 1) >> 1;                                    \
        j = j < 0 ? 0 : (j > 31 ? 31 : j);                          \
        int jm = j > 0 ? j - 1 : 0;                                 \
        int lj = __shfl_sync(FULLMASK, lab, j);                     \
        int lm = __shfl_sync(FULLMASK, lab, jm);                    \
        cls = ((s) & 1) ? lj : BLANK;                               \
        al  = (((s) & 1) && (j == 0 || lj != lm)) ? 1.0f : 0.0f;    \
    }
    STATE_SETUP(s0, cls0, al0);
    STATE_SETUP(s1, cls1, al1);
    STATE_SETUP(s2, cls2, al2);
#undef STATE_SETUP

    const bool v0 = (s0 < S), v1 = (s1 < S), v2 = (s2 < S);

    const float* base = y_pred + (size_t)b * T * C;

    // t = 0 init: alpha[0] = p(blank)+eps, alpha[1] = p(label0)+eps (no prescale)
    float r0 = 0.0f, r1 = 0.0f, r2 = 0.0f;
    if (lane == 0) {
        r0 = __ldg(base + BLANK) + EPS;
        r1 = __ldg(base + cls1)  + EPS;
    }

    // depth-8 register prefetch pipeline for the gathered probabilities
    float pa[8], pb[8], pc[8];
#pragma unroll
    for (int j = 0; j < 8; ++j) {
        const float* rp = base + (size_t)(1 + j) * C;
        float qa = __ldg(rp + cls0);
        float qb = __ldg(rp + cls1);
        float qc = __ldg(rp + cls2);
        pa[j] = v0 ? fmaf(qa, PRE, EPS_S) : 0.0f;
        pb[j] = v1 ? fmaf(qb, PRE, EPS_S) : 0.0f;
        pc[j] = v2 ? fmaf(qc, PRE, EPS_S) : 0.0f;
    }

    int Eacc = 0;   // accumulated base-2 exponent removed by renorms

    for (int tb = 1; tb < T; tb += 8) {
#pragma unroll
        for (int j = 0; j < 8; ++j) {
            const int t = tb + j;
            if (t < T) {
                const float p0 = pa[j], p1 = pb[j], p2 = pc[j];

                // prefetch step t+8 into the slot we just consumed
                const int tp = t + 8;
                if (tp < T) {
                    const float* rp = base + (size_t)tp * C;
                    float qa = __ldg(rp + cls0);
                    float qb = __ldg(rp + cls1);
                    float qc = __ldg(rp + cls2);
                    pa[j] = v0 ? fmaf(qa, PRE, EPS_S) : 0.0f;
                    pb[j] = v1 ? fmaf(qb, PRE, EPS_S) : 0.0f;
                    pc[j] = v2 ? fmaf(qc, PRE, EPS_S) : 0.0f;
                }

                // neighbor alphas: a[3i-1] = prev lane r2, a[3i-2] = prev lane r1
                float u1 = __shfl_up_sync(FULLMASK, r1, 1);
                float u2 = __shfl_up_sync(FULLMASK, r2, 1);
                if (lane == 0) { u1 = 0.0f; u2 = 0.0f; }

                const float n0 = p0 * fmaf(al0, u1, r0 + u2);
                const float n1 = p1 * fmaf(al1, u2, r1 + r0);
                const float n2 = p2 * fmaf(al2, r0, r2 + r1);
                r0 = n0; r1 = n1; r2 = n2;

                // renorm every 8 steps by an exact power of two
                if ((t & 7) == 0) {
                    float m = fmaxf(fmaxf(r0, r1), r2);
#pragma unroll
                    for (int o = 16; o; o >>= 1)
                        m = fmaxf(m, __shfl_xor_sync(FULLMASK, m, o));
                    const int e = (__float_as_int(m) >> 23) - 127;
                    const float sc = __int_as_float((127 - e) << 23); // 2^-e, exact
                    r0 *= sc; r1 *= sc; r2 *= sc;
                    Eacc += e;
                }
            }
        }
    }

    // loss = -logaddexp(alpha[2*len], alpha[2*len-1])  (JAX wraps -1 -> last)
    int ilb = 2 * len;
    int ill = 2 * len - 1;
    if (ill < 0) ill += S;

    const int lbL = ilb / 3, lbR = ilb % 3;
    const int llL = ill / 3, llR = ill % 3;
    const float g0 = __shfl_sync(FULLMASK, r0, lbL);
    const float g1 = __shfl_sync(FULLMASK, r1, lbL);
    const float g2 = __shfl_sync(FULLMASK, r2, lbL);
    const float h0 = __shfl_sync(FULLMASK, r0, llL);
    const float h1 = __shfl_sync(FULLMASK, r1, llL);
    const float h2 = __shfl_sync(FULLMASK, r2, llL);
    const float vlb = (lbR == 0) ? g0 : ((lbR == 1) ? g1 : g2);
    const float vll = (llR == 0) ? h0 : ((llR == 1) ? h1 : h2);

    if (lane == 0) {
        const float LN2 = 0.6931471805599453f;
        // stored = true * 2^(PRE_E*(T-1)) * 2^(-Eacc)
        float logsum = logf(vlb + vll) + (float)(Eacc - PRE_E * (T - 1)) * LN2;
        out[b] = -logsum;
    }
}

extern "C" void kernel_launch(void* const* d_in, const int* in_sizes, int n_in,
                              void* d_out, int out_size)
{
    (void)n_in; (void)out_size;
    const int*   y_true;
    const float* y_pred;
    // identify by element count: y_true = 256*32 = 8192, y_pred = 256*256*1024
    if (in_sizes[0] == 256 * 32) {
        y_true = (const int*)d_in[0];
        y_pred = (const float*)d_in[1];
    } else {
        y_true = (const int*)d_in[1];
        y_pred = (const float*)d_in[0];
    }
    // 256 batches, 1 warp each: 128 blocks x 64 threads
    ctc_fwd_kernel<<<128, 64>>>(y_true, y_pred, (float*)d_out);
}